// round 1
// baseline (speedup 1.0000x reference)
#include <cuda_runtime.h>
#include <math.h>

#define BATCH   8
#define TT      2048
#define BT      16384      // BATCH*TT
#define DMODEL  1024
#define NP      512        // padded projection columns (450 real)
#define RECW    516        // floats per (b,t) record

// ---------------- device scratch (no allocations allowed) ----------------
__device__ float g_WpT[DMODEL * NP];            // packed weights, [k][n]
__device__ float g_P[(size_t)BT * NP];          // raw projections
__device__ float g_rec[(size_t)BT * RECW];      // derived per-step records
__device__ float g_hs[(size_t)BT * 128];        // scan outputs
__device__ float g_CT[128 * DMODEL];            // C transposed, [n][d]

// ---------------- weight packing ----------------
// WpT[k][n]: n<64 -> W_A ; 64..319 -> W_k ; 320..321 -> W_beta ; 322..449 -> B_w ; else 0
__global__ void pack_w(const float* __restrict__ W_A, const float* __restrict__ W_k,
                       const float* __restrict__ W_beta, const float* __restrict__ B_w)
{
    int idx = blockIdx.x * 256 + threadIdx.x;
    if (idx >= DMODEL * NP) return;
    int k = idx / NP, n = idx % NP;
    float v = 0.f;
    if (n < 64)        v = W_A[n * DMODEL + k];
    else if (n < 320)  v = W_k[(size_t)(n - 64) * DMODEL + k];
    else if (n < 322)  v = W_beta[(n - 320) * DMODEL + k];
    else if (n < 450)  v = B_w[(size_t)(n - 322) * DMODEL + k];
    g_WpT[idx] = v;
}

__global__ void pack_c(const float* __restrict__ C)
{
    int idx = blockIdx.x * 256 + threadIdx.x;   // 128*1024
    if (idx >= 128 * DMODEL) return;
    int n = idx / DMODEL, d = idx % DMODEL;
    g_CT[idx] = C[(size_t)d * 128 + n];
}

// ---------------- SGEMM: 128x128 tile, BK=16, 256 threads, 8x8 micro ----------------
// WHICH==0: P[16384x512] = U[16384x1024] * WpT(k-major)      (plain store)
// WHICH==1: out[16384x1024] = hs[16384x128] * CT(k-major) + u*D
template <int WHICH>
__global__ __launch_bounds__(256)
void sgemm_kernel(const float* __restrict__ uPtr, float* __restrict__ outPtr,
                  const float* __restrict__ Dvec)
{
    constexpr int KTOT = (WHICH == 0) ? 1024 : 128;
    constexpr int LDA  = (WHICH == 0) ? 1024 : 128;
    constexpr int LDB  = (WHICH == 0) ? 512  : 1024;
    constexpr int LDC  = LDB;

    const float* A = (WHICH == 0) ? uPtr  : g_hs;
    const float* B = (WHICH == 0) ? g_WpT : g_CT;
    float*       Cc = (WHICH == 0) ? g_P  : outPtr;

    __shared__ float As[16][128];
    __shared__ float Bs[16][128];

    const int m0 = blockIdx.y * 128;
    const int n0 = blockIdx.x * 128;
    const int tid = threadIdx.x;
    const int tx = tid & 15, ty = tid >> 4;

    float acc[8][8];
#pragma unroll
    for (int i = 0; i < 8; i++)
#pragma unroll
        for (int j = 0; j < 8; j++) acc[i][j] = 0.f;

    for (int k0 = 0; k0 < KTOT; k0 += 16) {
        // A tile: 128 rows x 16 cols, transposed into As[k][m]
#pragma unroll
        for (int g = tid; g < 512; g += 256) {
            int row = g >> 2, cg = g & 3;
            float4 v = *(const float4*)(A + (size_t)(m0 + row) * LDA + k0 + cg * 4);
            As[cg * 4 + 0][row] = v.x;
            As[cg * 4 + 1][row] = v.y;
            As[cg * 4 + 2][row] = v.z;
            As[cg * 4 + 3][row] = v.w;
        }
        // B tile: 16 rows(k) x 128 cols(n), direct
#pragma unroll
        for (int g = tid; g < 512; g += 256) {
            int kk = g >> 5, ncg = g & 31;
            *(float4*)(&Bs[kk][ncg * 4]) =
                *(const float4*)(B + (size_t)(k0 + kk) * LDB + n0 + ncg * 4);
        }
        __syncthreads();

#pragma unroll
        for (int kk = 0; kk < 16; kk++) {
            float a[8], bb[8];
            *(float4*)(a)     = *(const float4*)(&As[kk][ty * 8]);
            *(float4*)(a + 4) = *(const float4*)(&As[kk][ty * 8 + 4]);
            *(float4*)(bb)     = *(const float4*)(&Bs[kk][tx * 8]);
            *(float4*)(bb + 4) = *(const float4*)(&Bs[kk][tx * 8 + 4]);
#pragma unroll
            for (int i = 0; i < 8; i++)
#pragma unroll
                for (int j = 0; j < 8; j++)
                    acc[i][j] = fmaf(a[i], bb[j], acc[i][j]);
        }
        __syncthreads();
    }

#pragma unroll
    for (int i = 0; i < 8; i++) {
        int row = m0 + ty * 8 + i;
        size_t base = (size_t)row * LDC + n0 + tx * 8;
        if (WHICH == 1) {
#pragma unroll
            for (int j = 0; j < 8; j++)
                Cc[base + j] = acc[i][j] + uPtr[base + j] * Dvec[n0 + tx * 8 + j];
        } else {
            float4 v0 = make_float4(acc[i][0], acc[i][1], acc[i][2], acc[i][3]);
            float4 v1 = make_float4(acc[i][4], acc[i][5], acc[i][6], acc[i][7]);
            *(float4*)(Cc + base)     = v0;
            *(float4*)(Cc + base + 4) = v1;
        }
    }
}

// ---------------- derive: raw projections -> per-step scan record ----------------
// record layout (floats): [0:64) S, [64:128) DT*A*S, [128:256) k1, [256:384) k2,
//                         [384:512) B, 512 beta1, 513 beta2, 514 cc=beta1*(k1.k2)
__global__ void derive_kernel(const float* __restrict__ bA, const float* __restrict__ bk,
                              const float* __restrict__ bbeta, const float* __restrict__ Bb)
{
    const int bt = blockIdx.x;
    const int n = threadIdx.x;               // 0..127
    const float* p = g_P + (size_t)bt * NP;
    float* rc = g_rec + (size_t)bt * RECW;

    if (n < 64) {
        float a = fminf(fmaxf(p[n] + bA[n], 0.f), 100.f);
        float S = 1.f / (1.f + 0.01f * a);
        rc[n]      = S;
        rc[64 + n] = 0.1f * a * S;           // DT*A*S
    }
    float k1 = p[64 + n]  + bk[n];
    float k2 = p[192 + n] + bk[128 + n];
    float Bv = p[322 + n] + Bb[n];

    float s1 = k1 * k1, s2 = k2 * k2, sx = k1 * k2;
#pragma unroll
    for (int off = 16; off; off >>= 1) {
        s1 += __shfl_xor_sync(0xffffffffu, s1, off);
        s2 += __shfl_xor_sync(0xffffffffu, s2, off);
        sx += __shfl_xor_sync(0xffffffffu, sx, off);
    }
    __shared__ float sm[12];
    __shared__ float bc[2];
    int w = n >> 5;
    if ((n & 31) == 0) { sm[w] = s1; sm[4 + w] = s2; sm[8 + w] = sx; }
    __syncthreads();
    if (n == 0) {
        float q1 = sm[0] + sm[1] + sm[2] + sm[3];
        float q2 = sm[4] + sm[5] + sm[6] + sm[7];
        float qx = sm[8] + sm[9] + sm[10] + sm[11];
        float i1 = 1.f / fmaxf(sqrtf(q1), 1e-12f);
        float i2 = 1.f / fmaxf(sqrtf(q2), 1e-12f);
        float be1 = 2.f / (1.f + expf(-(p[320] + bbeta[0])));
        float be2 = 2.f / (1.f + expf(-(p[321] + bbeta[1])));
        rc[512] = be1;
        rc[513] = be2;
        rc[514] = be1 * qx * i1 * i2;        // cc
        bc[0] = i1; bc[1] = i2;
    }
    __syncthreads();
    rc[128 + n] = k1 * bc[0];
    rc[256 + n] = k2 * bc[1];
    rc[384 + n] = Bv;
}

// ---------------- scan: one warp per batch, lane layout n = lane + 32*i ----------------
// i=0,1 -> z (m = lane, lane+32); i=2,3 -> y (same m). Rotation is lane-local.
// Two Householder updates folded: dot2' = dot2 - cc*dot1 (cc precomputed) ->
// both dots reduce in a single interleaved butterfly chain.
__global__ void scan_kernel()
{
    const int b = blockIdx.x;
    const int lane = threadIdx.x;
    const float* __restrict__ r = g_rec + (size_t)b * TT * RECW;
    float* __restrict__ o = g_hs + (size_t)b * TT * 128;

    float h0 = 0.f, h1 = 0.f, h2 = 0.f, h3 = 0.f;

    // load step 0
    float S0 = r[lane],        S1 = r[32 + lane];
    float D0 = r[64 + lane],   D1 = r[96 + lane];
    float A0 = r[128 + lane],  A1 = r[160 + lane], A2 = r[192 + lane], A3 = r[224 + lane];
    float C0 = r[256 + lane],  C1 = r[288 + lane], C2 = r[320 + lane], C3 = r[352 + lane];
    float B0 = r[384 + lane],  B1 = r[416 + lane], B2 = r[448 + lane], B3 = r[480 + lane];
    float be1 = r[512], be2 = r[513], cc = r[514];

    for (int t = 0; t < TT; t++) {
        const float* rn = r + ((t < TT - 1) ? RECW : 0);
        // prefetch next step (hides L2 latency under the butterfly)
        float nS0 = rn[lane],       nS1 = rn[32 + lane];
        float nD0 = rn[64 + lane],  nD1 = rn[96 + lane];
        float nA0 = rn[128 + lane], nA1 = rn[160 + lane], nA2 = rn[192 + lane], nA3 = rn[224 + lane];
        float nC0 = rn[256 + lane], nC1 = rn[288 + lane], nC2 = rn[320 + lane], nC3 = rn[352 + lane];
        float nB0 = rn[384 + lane], nB1 = rn[416 + lane], nB2 = rn[448 + lane], nB3 = rn[480 + lane];
        float nbe1 = rn[512], nbe2 = rn[513], ncc = rn[514];

        // rotation: z_new = S*z - (DT*A*S)*y ; y_new = S*(DT*z + y)
        float z0 = fmaf(-D0, h2, S0 * h0);
        float z1 = fmaf(-D1, h3, S1 * h1);
        float y2 = S0 * fmaf(0.1f, h0, h2);
        float y3 = S1 * fmaf(0.1f, h1, h3);

        // two dots, one butterfly chain
        float d1 = fmaf(A0, z0, A1 * z1); d1 = fmaf(A2, y2, d1); d1 = fmaf(A3, y3, d1);
        float d2 = fmaf(C0, z0, C1 * z1); d2 = fmaf(C2, y2, d2); d2 = fmaf(C3, y3, d2);
#pragma unroll
        for (int off = 16; off; off >>= 1) {
            d1 += __shfl_xor_sync(0xffffffffu, d1, off);
            d2 += __shfl_xor_sync(0xffffffffu, d2, off);
        }
        float a1 = be1 * d1;
        float a2 = be2 * fmaf(-cc, d1, d2);

        h0 = fmaf(-a2, C0, fmaf(-a1, A0, z0 + B0));
        h1 = fmaf(-a2, C1, fmaf(-a1, A1, z1 + B1));
        h2 = fmaf(-a2, C2, fmaf(-a1, A2, y2 + B2));
        h3 = fmaf(-a2, C3, fmaf(-a1, A3, y3 + B3));

        float* op = o + (size_t)t * 128;
        op[lane] = h0; op[32 + lane] = h1; op[64 + lane] = h2; op[96 + lane] = h3;

        r = rn;
        S0 = nS0; S1 = nS1; D0 = nD0; D1 = nD1;
        A0 = nA0; A1 = nA1; A2 = nA2; A3 = nA3;
        C0 = nC0; C1 = nC1; C2 = nC2; C3 = nC3;
        B0 = nB0; B1 = nB1; B2 = nB2; B3 = nB3;
        be1 = nbe1; be2 = nbe2; cc = ncc;
    }
}

// ---------------- launch ----------------
extern "C" void kernel_launch(void* const* d_in, const int* in_sizes, int n_in,
                              void* d_out, int out_size)
{
    const float* u      = (const float*)d_in[0];
    const float* W_A    = (const float*)d_in[1];
    const float* b_A    = (const float*)d_in[2];
    const float* W_k    = (const float*)d_in[3];
    const float* b_k    = (const float*)d_in[4];
    const float* W_beta = (const float*)d_in[5];
    const float* b_beta = (const float*)d_in[6];
    const float* B_w    = (const float*)d_in[7];
    const float* B_b    = (const float*)d_in[8];
    const float* C      = (const float*)d_in[9];
    const float* D      = (const float*)d_in[10];
    float* out = (float*)d_out;

    pack_w<<<(DMODEL * NP + 255) / 256, 256>>>(W_A, W_k, W_beta, B_w);
    pack_c<<<(128 * DMODEL + 255) / 256, 256>>>(C);

    sgemm_kernel<0><<<dim3(NP / 128, BT / 128), 256>>>(u, nullptr, nullptr);

    derive_kernel<<<BT, 128>>>(b_A, b_k, b_beta, B_b);

    scan_kernel<<<BATCH, 32>>>();

    sgemm_kernel<1><<<dim3(DMODEL / 128, BT / 128), 256>>>(u, out, D);
}

// round 2
// speedup vs baseline: 1.1064x; 1.1064x over previous
#include <cuda_runtime.h>
#include <cuda_bf16.h>
#include <math.h>

#define BATCH   8
#define TT      2048
#define BT      16384      // BATCH*TT
#define DMODEL  1024
#define NP      512        // padded projection columns (450 real)
#define RECW    516        // floats per (b,t) record
#define K1EXP   3072       // 3 * 1024  (bf16 split blocks: [hi, lo, hi])
#define K2EXP   384        // 3 * 128

// ---------------- device scratch (no allocations allowed) ----------------
__device__ __align__(16) __nv_bfloat16 g_Uexp[(size_t)BT * K1EXP];      // A for GEMM1, [bt][3K]
__device__ __align__(16) __nv_bfloat16 g_B1[(size_t)NP * K1EXP];        // B for GEMM1, [n][3K]
__device__ __align__(16) __nv_bfloat16 g_B2[(size_t)DMODEL * K2EXP];    // B for GEMM2, [d][3K]
__device__ __align__(16) __nv_bfloat16 g_Hexp[(size_t)BT * K2EXP];      // A for GEMM2 (scan out)
__device__ float g_P[(size_t)BT * NP];                                  // raw projections fp32
__device__ float g_rec[(size_t)BT * RECW];                              // derived scan records

// ---------------- helpers ----------------
__device__ __forceinline__ void split_bf16(float v, __nv_bfloat16& hi, __nv_bfloat16& lo)
{
    hi = __float2bfloat16(v);
    lo = __float2bfloat16(v - __bfloat162float(hi));
}

// ---------------- U -> bf16 hi/lo expansion: Uexp[bt][3K] = [hi | lo | hi] ----------------
__global__ void conv_u(const float* __restrict__ u)
{
    size_t i = (size_t)blockIdx.x * 256 + threadIdx.x;   // one group of 4 floats
    size_t row = i >> 8;                                  // 1024/4 = 256 groups per row
    int c = (int)(i & 255) * 4;
    float4 v = *(const float4*)(u + row * DMODEL + c);
    __nv_bfloat16 h[4], l[4];
    split_bf16(v.x, h[0], l[0]); split_bf16(v.y, h[1], l[1]);
    split_bf16(v.z, h[2], l[2]); split_bf16(v.w, h[3], l[3]);
    __nv_bfloat16* base = g_Uexp + row * K1EXP;
    *(uint2*)(base + c)        = *(uint2*)h;   // block0: hi
    *(uint2*)(base + 1024 + c) = *(uint2*)l;   // block1: lo
    *(uint2*)(base + 2048 + c) = *(uint2*)h;   // block2: hi
}

// ---------------- pack B1[n][3K]: blocks [Bh | Bh | Bl] ----------------
// col mapping: n<64 -> W_A ; 64..319 -> W_k ; 320..321 -> W_beta ; 322..449 -> B_w ; else 0
__global__ void pack_b1(const float* __restrict__ W_A, const float* __restrict__ W_k,
                        const float* __restrict__ W_beta, const float* __restrict__ B_w)
{
    int idx = blockIdx.x * 256 + threadIdx.x;            // NP * 1024
    if (idx >= NP * DMODEL) return;
    int n = idx >> 10, k = idx & 1023;
    float v = 0.f;
    if (n < 64)        v = W_A[n * DMODEL + k];
    else if (n < 320)  v = W_k[(size_t)(n - 64) * DMODEL + k];
    else if (n < 322)  v = W_beta[(n - 320) * DMODEL + k];
    else if (n < 450)  v = B_w[(size_t)(n - 322) * DMODEL + k];
    __nv_bfloat16 hi, lo; split_bf16(v, hi, lo);
    __nv_bfloat16* base = g_B1 + (size_t)n * K1EXP;
    base[k] = hi; base[1024 + k] = hi; base[2048 + k] = lo;
}

// ---------------- pack B2[d][3*128]: blocks [Ch | Ch | Cl], C is [d][n] ----------------
__global__ void pack_b2(const float* __restrict__ C)
{
    int idx = blockIdx.x * 256 + threadIdx.x;            // DMODEL * 128
    if (idx >= DMODEL * 128) return;
    int d = idx >> 7, n = idx & 127;
    float v = C[(size_t)d * 128 + n];
    __nv_bfloat16 hi, lo; split_bf16(v, hi, lo);
    __nv_bfloat16* base = g_B2 + (size_t)d * K2EXP;
    base[n] = hi; base[128 + n] = hi; base[256 + n] = lo;
}

// ---------------- bf16 HMMA GEMM: 128x128 tile, BK=32, 256 threads, 8 warps (4x2) ----------
// A row-major [M][KTOT] bf16, B n-major [N][KTOT] bf16 ("col" operand), C fp32 [M][ldc].
// If uPtr != null: C += u * D elementwise (GEMM2 epilogue).
// SMEM word swizzle: word index w (0..15 per row) stored at w ^ ((row&7)<<1) -> all
// fragment LDS.b32 patterns are 32-bank conflict-free; uint2 granularity preserved.
template <int KTOT, int LDA, int LDB>
__global__ __launch_bounds__(256)
void mma_gemm(const __nv_bfloat16* __restrict__ A, const __nv_bfloat16* __restrict__ B,
              float* __restrict__ Cout, int ldc,
              const float* __restrict__ uPtr, const float* __restrict__ Dvec)
{
    __shared__ unsigned sA[2][128 * 16];
    __shared__ unsigned sB[2][128 * 16];

    const int tid  = threadIdx.x;
    const int m0   = blockIdx.y * 128;
    const int n0   = blockIdx.x * 128;
    const int lrow = tid >> 1, half = tid & 1;           // gmem staging: row, k-half
    const int wid  = tid >> 5, lane = tid & 31;
    const int wm   = wid >> 1, wn = wid & 1;             // warp 32(M) x 64(N)
    const int grp  = lane >> 2, tig = lane & 3;

    const uint4* Ag = (const uint4*)A + (size_t)(m0 + lrow) * (LDA / 8) + half * 2;
    const uint4* Bg = (const uint4*)B + (size_t)(n0 + lrow) * (LDB / 8) + half * 2;

    const int sw    = (lrow & 7) << 1;
    const int sbase = lrow * 16;
    const int w0    = half * 8;

    float acc[2][8][4];
#pragma unroll
    for (int im = 0; im < 2; im++)
#pragma unroll
        for (int in = 0; in < 8; in++)
#pragma unroll
            for (int q = 0; q < 4; q++) acc[im][in][q] = 0.f;

    constexpr int KIT = KTOT / 32;

    uint4 pa0 = Ag[0], pa1 = Ag[1], pb0 = Bg[0], pb1 = Bg[1];
    Ag += 4; Bg += 4;

#define STILE(dst, v0, v1)                                                              \
    do {                                                                                \
        ((uint2*)(dst))[(sbase + ((w0 + 0) ^ sw)) >> 1] = make_uint2((v0).x, (v0).y);   \
        ((uint2*)(dst))[(sbase + ((w0 + 2) ^ sw)) >> 1] = make_uint2((v0).z, (v0).w);   \
        ((uint2*)(dst))[(sbase + ((w0 + 4) ^ sw)) >> 1] = make_uint2((v1).x, (v1).y);   \
        ((uint2*)(dst))[(sbase + ((w0 + 6) ^ sw)) >> 1] = make_uint2((v1).z, (v1).w);   \
    } while (0)

    STILE(sA[0], pa0, pa1);
    STILE(sB[0], pb0, pb1);
    __syncthreads();

    for (int it = 0; it < KIT; it++) {
        const int cur = it & 1, nxt = cur ^ 1;
        if (it + 1 < KIT) {
            pa0 = Ag[0]; pa1 = Ag[1]; pb0 = Bg[0]; pb1 = Bg[1];
            Ag += 4; Bg += 4;
        }
        const unsigned* cA = sA[cur];
        const unsigned* cB = sB[cur];

#pragma unroll
        for (int kk = 0; kk < 2; kk++) {
            unsigned af[2][4], bf[8][2];
#pragma unroll
            for (int im = 0; im < 2; im++) {
                int r0 = wm * 32 + im * 16 + grp;
                int r1 = r0 + 8;
                int s0 = (r0 & 7) << 1;
                int s1 = (r1 & 7) << 1;
                af[im][0] = cA[r0 * 16 + ((kk * 8 + tig) ^ s0)];
                af[im][1] = cA[r1 * 16 + ((kk * 8 + tig) ^ s1)];
                af[im][2] = cA[r0 * 16 + ((kk * 8 + 4 + tig) ^ s0)];
                af[im][3] = cA[r1 * 16 + ((kk * 8 + 4 + tig) ^ s1)];
            }
#pragma unroll
            for (int in = 0; in < 8; in++) {
                int nr = wn * 64 + in * 8 + grp;
                int s  = (nr & 7) << 1;
                bf[in][0] = cB[nr * 16 + ((kk * 8 + tig) ^ s)];
                bf[in][1] = cB[nr * 16 + ((kk * 8 + 4 + tig) ^ s)];
            }
#pragma unroll
            for (int im = 0; im < 2; im++)
#pragma unroll
                for (int in = 0; in < 8; in++) {
                    float* c = acc[im][in];
                    asm volatile(
                        "mma.sync.aligned.m16n8k16.row.col.f32.bf16.bf16.f32 "
                        "{%0,%1,%2,%3}, {%4,%5,%6,%7}, {%8,%9}, {%0,%1,%2,%3};\n"
                        : "+f"(c[0]), "+f"(c[1]), "+f"(c[2]), "+f"(c[3])
                        : "r"(af[im][0]), "r"(af[im][1]), "r"(af[im][2]), "r"(af[im][3]),
                          "r"(bf[in][0]), "r"(bf[in][1]));
                }
        }

        if (it + 1 < KIT) {
            STILE(sA[nxt], pa0, pa1);
            STILE(sB[nxt], pb0, pb1);
            __syncthreads();
        }
    }
#undef STILE

    // epilogue
#pragma unroll
    for (int im = 0; im < 2; im++) {
#pragma unroll
        for (int in = 0; in < 8; in++) {
            int row = m0 + wm * 32 + im * 16 + grp;
            int col = n0 + wn * 64 + in * 8 + tig * 2;
            float2 v01 = make_float2(acc[im][in][0], acc[im][in][1]);
            float2 v23 = make_float2(acc[im][in][2], acc[im][in][3]);
            if (uPtr) {
                size_t b0 = (size_t)row * ldc + col;
                size_t b1 = (size_t)(row + 8) * ldc + col;
                v01.x += uPtr[b0] * Dvec[col];
                v01.y += uPtr[b0 + 1] * Dvec[col + 1];
                v23.x += uPtr[b1] * Dvec[col];
                v23.y += uPtr[b1 + 1] * Dvec[col + 1];
            }
            *(float2*)(Cout + (size_t)row * ldc + col)       = v01;
            *(float2*)(Cout + (size_t)(row + 8) * ldc + col) = v23;
        }
    }
}

// ---------------- derive: raw projections -> per-step scan record ----------------
// record layout: [0:64) S, [64:128) DT*A*S, [128:256) k1, [256:384) k2,
//                [384:512) B, 512 beta1, 513 beta2, 514 cc=beta1*(k1.k2)
__global__ void derive_kernel(const float* __restrict__ bA, const float* __restrict__ bk,
                              const float* __restrict__ bbeta, const float* __restrict__ Bb)
{
    const int bt = blockIdx.x;
    const int n = threadIdx.x;               // 0..127
    const float* p = g_P + (size_t)bt * NP;
    float* rc = g_rec + (size_t)bt * RECW;

    if (n < 64) {
        float a = fminf(fmaxf(p[n] + bA[n], 0.f), 100.f);
        float S = 1.f / (1.f + 0.01f * a);
        rc[n]      = S;
        rc[64 + n] = 0.1f * a * S;           // DT*A*S
    }
    float k1 = p[64 + n]  + bk[n];
    float k2 = p[192 + n] + bk[128 + n];
    float Bv = p[322 + n] + Bb[n];

    float s1 = k1 * k1, s2 = k2 * k2, sx = k1 * k2;
#pragma unroll
    for (int off = 16; off; off >>= 1) {
        s1 += __shfl_xor_sync(0xffffffffu, s1, off);
        s2 += __shfl_xor_sync(0xffffffffu, s2, off);
        sx += __shfl_xor_sync(0xffffffffu, sx, off);
    }
    __shared__ float sm[12];
    __shared__ float bc[2];
    int w = n >> 5;
    if ((n & 31) == 0) { sm[w] = s1; sm[4 + w] = s2; sm[8 + w] = sx; }
    __syncthreads();
    if (n == 0) {
        float q1 = sm[0] + sm[1] + sm[2] + sm[3];
        float q2 = sm[4] + sm[5] + sm[6] + sm[7];
        float qx = sm[8] + sm[9] + sm[10] + sm[11];
        float i1 = 1.f / fmaxf(sqrtf(q1), 1e-12f);
        float i2 = 1.f / fmaxf(sqrtf(q2), 1e-12f);
        float be1 = 2.f / (1.f + expf(-(p[320] + bbeta[0])));
        float be2 = 2.f / (1.f + expf(-(p[321] + bbeta[1])));
        rc[512] = be1;
        rc[513] = be2;
        rc[514] = be1 * qx * i1 * i2;        // cc
        bc[0] = i1; bc[1] = i2;
    }
    __syncthreads();
    rc[128 + n] = k1 * bc[0];
    rc[256 + n] = k2 * bc[1];
    rc[384 + n] = Bv;
}

// ---------------- scan: one warp per batch, lane layout n = lane + 32*i ----------------
// Outputs go straight to bf16 hi/lo blocks for GEMM2 (no fp32 hs array).
__global__ void scan_kernel()
{
    const int b = blockIdx.x;
    const int lane = threadIdx.x;
    const float* __restrict__ r = g_rec + (size_t)b * TT * RECW;
    __nv_bfloat16* __restrict__ o = g_Hexp + (size_t)b * TT * K2EXP;

    float h0 = 0.f, h1 = 0.f, h2 = 0.f, h3 = 0.f;

    float S0 = r[lane],        S1 = r[32 + lane];
    float D0 = r[64 + lane],   D1 = r[96 + lane];
    float A0 = r[128 + lane],  A1 = r[160 + lane], A2 = r[192 + lane], A3 = r[224 + lane];
    float C0 = r[256 + lane],  C1 = r[288 + lane], C2 = r[320 + lane], C3 = r[352 + lane];
    float B0 = r[384 + lane],  B1 = r[416 + lane], B2 = r[448 + lane], B3 = r[480 + lane];
    float be1 = r[512], be2 = r[513], cc = r[514];

    for (int t = 0; t < TT; t++) {
        const float* rn = r + ((t < TT - 1) ? RECW : 0);
        float nS0 = rn[lane],       nS1 = rn[32 + lane];
        float nD0 = rn[64 + lane],  nD1 = rn[96 + lane];
        float nA0 = rn[128 + lane], nA1 = rn[160 + lane], nA2 = rn[192 + lane], nA3 = rn[224 + lane];
        float nC0 = rn[256 + lane], nC1 = rn[288 + lane], nC2 = rn[320 + lane], nC3 = rn[352 + lane];
        float nB0 = rn[384 + lane], nB1 = rn[416 + lane], nB2 = rn[448 + lane], nB3 = rn[480 + lane];
        float nbe1 = rn[512], nbe2 = rn[513], ncc = rn[514];

        float z0 = fmaf(-D0, h2, S0 * h0);
        float z1 = fmaf(-D1, h3, S1 * h1);
        float y2 = S0 * fmaf(0.1f, h0, h2);
        float y3 = S1 * fmaf(0.1f, h1, h3);

        float d1 = fmaf(A0, z0, A1 * z1); d1 = fmaf(A2, y2, d1); d1 = fmaf(A3, y3, d1);
        float d2 = fmaf(C0, z0, C1 * z1); d2 = fmaf(C2, y2, d2); d2 = fmaf(C3, y3, d2);
#pragma unroll
        for (int off = 16; off; off >>= 1) {
            d1 += __shfl_xor_sync(0xffffffffu, d1, off);
            d2 += __shfl_xor_sync(0xffffffffu, d2, off);
        }
        float a1 = be1 * d1;
        float a2 = be2 * fmaf(-cc, d1, d2);

        h0 = fmaf(-a2, C0, fmaf(-a1, A0, z0 + B0));
        h1 = fmaf(-a2, C1, fmaf(-a1, A1, z1 + B1));
        h2 = fmaf(-a2, C2, fmaf(-a1, A2, y2 + B2));
        h3 = fmaf(-a2, C3, fmaf(-a1, A3, y3 + B3));

        __nv_bfloat16* op = o + (size_t)t * K2EXP;
        __nv_bfloat16 hh0, hl0, hh1, hl1, hh2, hl2, hh3, hl3;
        split_bf16(h0, hh0, hl0); split_bf16(h1, hh1, hl1);
        split_bf16(h2, hh2, hl2); split_bf16(h3, hh3, hl3);
        op[lane]       = hh0; op[32 + lane]  = hh1; op[64 + lane]  = hh2; op[96 + lane]  = hh3;
        op[128 + lane] = hl0; op[160 + lane] = hl1; op[192 + lane] = hl2; op[224 + lane] = hl3;
        op[256 + lane] = hh0; op[288 + lane] = hh1; op[320 + lane] = hh2; op[352 + lane] = hh3;

        r = rn;
        S0 = nS0; S1 = nS1; D0 = nD0; D1 = nD1;
        A0 = nA0; A1 = nA1; A2 = nA2; A3 = nA3;
        C0 = nC0; C1 = nC1; C2 = nC2; C3 = nC3;
        B0 = nB0; B1 = nB1; B2 = nB2; B3 = nB3;
        be1 = nbe1; be2 = nbe2; cc = ncc;
    }
}

// ---------------- launch ----------------
extern "C" void kernel_launch(void* const* d_in, const int* in_sizes, int n_in,
                              void* d_out, int out_size)
{
    const float* u      = (const float*)d_in[0];
    const float* W_A    = (const float*)d_in[1];
    const float* b_A    = (const float*)d_in[2];
    const float* W_k    = (const float*)d_in[3];
    const float* b_k    = (const float*)d_in[4];
    const float* W_beta = (const float*)d_in[5];
    const float* b_beta = (const float*)d_in[6];
    const float* B_w    = (const float*)d_in[7];
    const float* B_b    = (const float*)d_in[8];
    const float* C      = (const float*)d_in[9];
    const float* D      = (const float*)d_in[10];
    float* out = (float*)d_out;

    conv_u<<<(BT * (DMODEL / 4)) / 256, 256>>>(u);
    pack_b1<<<(NP * DMODEL + 255) / 256, 256>>>(W_A, W_k, W_beta, B_w);
    pack_b2<<<(DMODEL * 128 + 255) / 256, 256>>>(C);

    // GEMM1: P[16384 x 512] = Uexp[16384 x 3072] * B1^T
    {
        __nv_bfloat16 *dA, *dB; float* dP;
        cudaGetSymbolAddress((void**)&dA, g_Uexp);
        cudaGetSymbolAddress((void**)&dB, g_B1);
        cudaGetSymbolAddress((void**)&dP, g_P);
        mma_gemm<K1EXP, K1EXP, K1EXP><<<dim3(NP / 128, BT / 128), 256>>>(
            dA, dB, dP, NP, nullptr, nullptr);
    }

    derive_kernel<<<BT, 128>>>(b_A, b_k, b_beta, B_b);

    scan_kernel<<<BATCH, 32>>>();

    // GEMM2: out[16384 x 1024] = Hexp[16384 x 384] * B2^T + u * D
    {
        __nv_bfloat16 *dA, *dB;
        cudaGetSymbolAddress((void**)&dA, g_Hexp);
        cudaGetSymbolAddress((void**)&dB, g_B2);
        mma_gemm<K2EXP, K2EXP, K2EXP><<<dim3(DMODEL / 128, BT / 128), 256>>>(
            dA, dB, out, DMODEL, u, D);
    }
}

// round 4
// speedup vs baseline: 1.8110x; 1.6369x over previous
#include <cuda_runtime.h>
#include <cuda_bf16.h>
#include <math.h>

#define BATCH   8
#define TT      2048
#define BT      16384      // BATCH*TT
#define DMODEL  1024
#define NP      512        // padded projection columns (450 real)
#define RECW    516        // floats per (b,t) record (multiple of 4 -> float4 aligned)
#define K1EXP   3072       // 3 * 1024  (bf16 split blocks: [hi, lo, hi])
#define K2EXP   384        // 12 * 32   (interleaved per-lane triplets, see scan)

// ---------------- device scratch (no allocations allowed) ----------------
__device__ __align__(16) __nv_bfloat16 g_Uexp[(size_t)BT * K1EXP];      // A for GEMM1, [bt][3K]
__device__ __align__(16) __nv_bfloat16 g_B1[(size_t)NP * K1EXP];        // B for GEMM1, [n][3K]
__device__ __align__(16) __nv_bfloat16 g_B2[(size_t)DMODEL * K2EXP];    // B for GEMM2, [d][384]
__device__ __align__(16) __nv_bfloat16 g_Hexp[(size_t)BT * K2EXP];      // A for GEMM2 (scan out)
__device__ float g_P[(size_t)BT * NP];                                  // raw projections fp32
__device__ __align__(16) float g_rec[(size_t)BT * RECW];                // derived scan records

// ---------------- helpers ----------------
__device__ __forceinline__ void split_bf16(float v, __nv_bfloat16& hi, __nv_bfloat16& lo)
{
    hi = __float2bfloat16(v);
    lo = __float2bfloat16(v - __bfloat162float(hi));
}

__device__ __forceinline__ unsigned pack2(__nv_bfloat16 a, __nv_bfloat16 b)
{
    __nv_bfloat162 p(a, b);
    return *(unsigned*)&p;
}

// ---------------- U -> bf16 hi/lo expansion: Uexp[bt][3K] = [hi | lo | hi] ----------------
__global__ void conv_u(const float* __restrict__ u)
{
    size_t i = (size_t)blockIdx.x * 256 + threadIdx.x;   // one group of 4 floats
    size_t row = i >> 8;                                  // 1024/4 = 256 groups per row
    int c = (int)(i & 255) * 4;
    float4 v = *(const float4*)(u + row * DMODEL + c);
    __nv_bfloat16 h[4], l[4];
    split_bf16(v.x, h[0], l[0]); split_bf16(v.y, h[1], l[1]);
    split_bf16(v.z, h[2], l[2]); split_bf16(v.w, h[3], l[3]);
    __nv_bfloat16* base = g_Uexp + row * K1EXP;
    *(uint2*)(base + c)        = *(uint2*)h;   // block0: hi
    *(uint2*)(base + 1024 + c) = *(uint2*)l;   // block1: lo
    *(uint2*)(base + 2048 + c) = *(uint2*)h;   // block2: hi
}

// ---------------- pack B1[n][3K]: blocks [Bh | Bh | Bl] ----------------
// col mapping: n<64 -> W_A ; 64..319 -> W_k ; 320..321 -> W_beta ; 322..449 -> B_w ; else 0
__global__ void pack_b1(const float* __restrict__ W_A, const float* __restrict__ W_k,
                        const float* __restrict__ W_beta, const float* __restrict__ B_w)
{
    int idx = blockIdx.x * 256 + threadIdx.x;            // NP * 1024
    if (idx >= NP * DMODEL) return;
    int n = idx >> 10, k = idx & 1023;
    float v = 0.f;
    if (n < 64)        v = W_A[n * DMODEL + k];
    else if (n < 320)  v = W_k[(size_t)(n - 64) * DMODEL + k];
    else if (n < 322)  v = W_beta[(n - 320) * DMODEL + k];
    else if (n < 450)  v = B_w[(size_t)(n - 322) * DMODEL + k];
    __nv_bfloat16 hi, lo; split_bf16(v, hi, lo);
    __nv_bfloat16* base = g_B1 + (size_t)n * K1EXP;
    base[k] = hi; base[1024 + k] = hi; base[2048 + k] = lo;
}

// ---------------- pack B2[d][384]: k = 12*l + 3*i + s ; s0=Ch s1=Ch s2=Cl, n=l+32i ------
__global__ void pack_b2(const float* __restrict__ C)
{
    int idx = blockIdx.x * 256 + threadIdx.x;            // DMODEL * 128
    if (idx >= DMODEL * 128) return;
    int d = idx >> 7, n = idx & 127;
    int l = n & 31, i = n >> 5;
    float v = C[(size_t)d * 128 + n];
    __nv_bfloat16 hi, lo; split_bf16(v, hi, lo);
    __nv_bfloat16* base = g_B2 + (size_t)d * K2EXP + 12 * l + 3 * i;
    base[0] = hi; base[1] = hi; base[2] = lo;
}

// ---------------- bf16 HMMA GEMM: 128x128 tile, BK=32, 256 threads, 8 warps (4x2) ----------
template <int KTOT, int LDA, int LDB>
__global__ __launch_bounds__(256)
void mma_gemm(const __nv_bfloat16* __restrict__ A, const __nv_bfloat16* __restrict__ B,
              float* __restrict__ Cout, int ldc,
              const float* __restrict__ uPtr, const float* __restrict__ Dvec)
{
    __shared__ unsigned sA[2][128 * 16];
    __shared__ unsigned sB[2][128 * 16];

    const int tid  = threadIdx.x;
    const int m0   = blockIdx.y * 128;
    const int n0   = blockIdx.x * 128;
    const int lrow = tid >> 1, half = tid & 1;           // gmem staging: row, k-half
    const int wid  = tid >> 5, lane = tid & 31;
    const int wm   = wid >> 1, wn = wid & 1;             // warp 32(M) x 64(N)
    const int grp  = lane >> 2, tig = lane & 3;

    const uint4* Ag = (const uint4*)A + (size_t)(m0 + lrow) * (LDA / 8) + half * 2;
    const uint4* Bg = (const uint4*)B + (size_t)(n0 + lrow) * (LDB / 8) + half * 2;

    const int sw    = (lrow & 7) << 1;
    const int sbase = lrow * 16;
    const int w0    = half * 8;

    float acc[2][8][4];
#pragma unroll
    for (int im = 0; im < 2; im++)
#pragma unroll
        for (int in = 0; in < 8; in++)
#pragma unroll
            for (int q = 0; q < 4; q++) acc[im][in][q] = 0.f;

    constexpr int KIT = KTOT / 32;

    uint4 pa0 = Ag[0], pa1 = Ag[1], pb0 = Bg[0], pb1 = Bg[1];
    Ag += 4; Bg += 4;

#define STILE(dst, v0, v1)                                                              \
    do {                                                                                \
        ((uint2*)(dst))[(sbase + ((w0 + 0) ^ sw)) >> 1] = make_uint2((v0).x, (v0).y);   \
        ((uint2*)(dst))[(sbase + ((w0 + 2) ^ sw)) >> 1] = make_uint2((v0).z, (v0).w);   \
        ((uint2*)(dst))[(sbase + ((w0 + 4) ^ sw)) >> 1] = make_uint2((v1).x, (v1).y);   \
        ((uint2*)(dst))[(sbase + ((w0 + 6) ^ sw)) >> 1] = make_uint2((v1).z, (v1).w);   \
    } while (0)

    STILE(sA[0], pa0, pa1);
    STILE(sB[0], pb0, pb1);
    __syncthreads();

    for (int it = 0; it < KIT; it++) {
        const int cur = it & 1, nxt = cur ^ 1;
        if (it + 1 < KIT) {
            pa0 = Ag[0]; pa1 = Ag[1]; pb0 = Bg[0]; pb1 = Bg[1];
            Ag += 4; Bg += 4;
        }
        const unsigned* cA = sA[cur];
        const unsigned* cB = sB[cur];

#pragma unroll
        for (int kk = 0; kk < 2; kk++) {
            unsigned af[2][4], bf[8][2];
#pragma unroll
            for (int im = 0; im < 2; im++) {
                int r0 = wm * 32 + im * 16 + grp;
                int r1 = r0 + 8;
                int s0 = (r0 & 7) << 1;
                int s1 = (r1 & 7) << 1;
                af[im][0] = cA[r0 * 16 + ((kk * 8 + tig) ^ s0)];
                af[im][1] = cA[r1 * 16 + ((kk * 8 + tig) ^ s1)];
                af[im][2] = cA[r0 * 16 + ((kk * 8 + 4 + tig) ^ s0)];
                af[im][3] = cA[r1 * 16 + ((kk * 8 + 4 + tig) ^ s1)];
            }
#pragma unroll
            for (int in = 0; in < 8; in++) {
                int nr = wn * 64 + in * 8 + grp;
                int s  = (nr & 7) << 1;
                bf[in][0] = cB[nr * 16 + ((kk * 8 + tig) ^ s)];
                bf[in][1] = cB[nr * 16 + ((kk * 8 + 4 + tig) ^ s)];
            }
#pragma unroll
            for (int im = 0; im < 2; im++)
#pragma unroll
                for (int in = 0; in < 8; in++) {
                    float* c = acc[im][in];
                    asm volatile(
                        "mma.sync.aligned.m16n8k16.row.col.f32.bf16.bf16.f32 "
                        "{%0,%1,%2,%3}, {%4,%5,%6,%7}, {%8,%9}, {%0,%1,%2,%3};\n"
                        : "+f"(c[0]), "+f"(c[1]), "+f"(c[2]), "+f"(c[3])
                        : "r"(af[im][0]), "r"(af[im][1]), "r"(af[im][2]), "r"(af[im][3]),
                          "r"(bf[in][0]), "r"(bf[in][1]));
                }
        }

        if (it + 1 < KIT) {
            STILE(sA[nxt], pa0, pa1);
            STILE(sB[nxt], pb0, pb1);
            __syncthreads();
        }
    }
#undef STILE

    // epilogue
#pragma unroll
    for (int im = 0; im < 2; im++) {
#pragma unroll
        for (int in = 0; in < 8; in++) {
            int row = m0 + wm * 32 + im * 16 + grp;
            int col = n0 + wn * 64 + in * 8 + tig * 2;
            float2 v01 = make_float2(acc[im][in][0], acc[im][in][1]);
            float2 v23 = make_float2(acc[im][in][2], acc[im][in][3]);
            if (uPtr) {
                size_t b0 = (size_t)row * ldc + col;
                size_t b1 = (size_t)(row + 8) * ldc + col;
                v01.x += uPtr[b0] * Dvec[col];
                v01.y += uPtr[b0 + 1] * Dvec[col + 1];
                v23.x += uPtr[b1] * Dvec[col];
                v23.y += uPtr[b1 + 1] * Dvec[col + 1];
            }
            *(float2*)(Cout + (size_t)row * ldc + col)       = v01;
            *(float2*)(Cout + (size_t)(row + 8) * ldc + col) = v23;
        }
    }
}

// ---------------- derive: raw projections -> per-step scan record (float4-lane layout) ----
// record floats: [0,128)   vec0: lane l -> (S0,S1,D0,D1) at 4l
//                [128,256) vec1: 4l+i = k1n   (n = l+32i)
//                [256,384) vec2: 4l+i = k2n
//                [384,512) vec3: 4l+i = B
//                [512] be1, [513] be2, [514] cc, [515] pad
__global__ void derive_kernel(const float* __restrict__ bA, const float* __restrict__ bk,
                              const float* __restrict__ bbeta, const float* __restrict__ Bb)
{
    const int bt = blockIdx.x;
    const int n = threadIdx.x;               // 0..127
    const int l = n & 31, i = n >> 5;
    const float* p = g_P + (size_t)bt * NP;
    float* rc = g_rec + (size_t)bt * RECW;

    if (n < 64) {
        float a = fminf(fmaxf(p[n] + bA[n], 0.f), 100.f);
        float S = 1.f / (1.f + 0.01f * a);
        rc[4 * l + i]     = S;
        rc[4 * l + 2 + i] = 0.1f * a * S;    // DT*A*S
    }
    float k1 = p[64 + n]  + bk[n];
    float k2 = p[192 + n] + bk[128 + n];
    float Bv = p[322 + n] + Bb[n];

    float s1 = k1 * k1, s2 = k2 * k2, sx = k1 * k2;
#pragma unroll
    for (int off = 16; off; off >>= 1) {
        s1 += __shfl_xor_sync(0xffffffffu, s1, off);
        s2 += __shfl_xor_sync(0xffffffffu, s2, off);
        sx += __shfl_xor_sync(0xffffffffu, sx, off);
    }
    __shared__ float sm[12];
    __shared__ float bc[2];
    int w = n >> 5;
    if ((n & 31) == 0) { sm[w] = s1; sm[4 + w] = s2; sm[8 + w] = sx; }
    __syncthreads();
    if (n == 0) {
        float q1 = sm[0] + sm[1] + sm[2] + sm[3];
        float q2 = sm[4] + sm[5] + sm[6] + sm[7];
        float qx = sm[8] + sm[9] + sm[10] + sm[11];
        float i1 = 1.f / fmaxf(sqrtf(q1), 1e-12f);
        float i2 = 1.f / fmaxf(sqrtf(q2), 1e-12f);
        float be1 = 2.f / (1.f + expf(-(p[320] + bbeta[0])));
        float be2 = 2.f / (1.f + expf(-(p[321] + bbeta[1])));
        rc[512] = be1;
        rc[513] = be2;
        rc[514] = be1 * qx * i1 * i2;        // cc
        bc[0] = i1; bc[1] = i2;
    }
    __syncthreads();
    rc[128 + 4 * l + i] = k1 * bc[0];
    rc[256 + 4 * l + i] = k2 * bc[1];
    rc[384 + 4 * l + i] = Bv;
}

// ---------------- scan: one warp per batch; float4 loads, butterfly reductions, packed stores
// Output k-layout (matching pack_b2): k = 12*l + 3*i + {hh_i, hl_i, hh_i}
__global__ void scan_kernel()
{
    const int b = blockIdx.x;
    const int lane = threadIdx.x;
    const float4* __restrict__ r4 = (const float4*)g_rec + (size_t)b * TT * (RECW / 4);
    __nv_bfloat16* __restrict__ o = g_Hexp + (size_t)b * TT * K2EXP;

    float h0 = 0.f, h1 = 0.f, h2 = 0.f, h3 = 0.f;

    float4 sv[4], av[4], cv[4], bv[4], ev[4];
#pragma unroll
    for (int p = 0; p < 4; p++) {
        const float4* rp = r4 + (size_t)p * (RECW / 4);
        sv[p] = rp[lane];
        av[p] = rp[32 + lane];
        cv[p] = rp[64 + lane];
        bv[p] = rp[96 + lane];
        ev[p] = rp[128];
    }

#pragma unroll 4
    for (int t = 0; t < TT; t++) {
        const int s = t & 3;
        const float4 S = sv[s], A = av[s], Cv = cv[s], Bv = bv[s], E = ev[s];

        const int tn = t + 4;
        if (tn < TT) {
            const float4* rp = r4 + (size_t)tn * (RECW / 4);
            sv[s] = rp[lane];
            av[s] = rp[32 + lane];
            cv[s] = rp[64 + lane];
            bv[s] = rp[96 + lane];
            ev[s] = rp[128];
        }

        // rotation: z_new = S*z - (DT*A*S)*y ; y_new = S*(DT*z + y)
        float z0 = fmaf(-S.z, h2, S.x * h0);
        float z1 = fmaf(-S.w, h3, S.y * h1);
        float y2 = S.x * fmaf(0.1f, h0, h2);
        float y3 = S.y * fmaf(0.1f, h1, h3);

        // two dots, one interleaved butterfly chain
        float d1 = fmaf(A.x, z0, A.y * z1); d1 = fmaf(A.z, y2, d1); d1 = fmaf(A.w, y3, d1);
        float d2 = fmaf(Cv.x, z0, Cv.y * z1); d2 = fmaf(Cv.z, y2, d2); d2 = fmaf(Cv.w, y3, d2);
#pragma unroll
        for (int off = 16; off; off >>= 1) {
            d1 += __shfl_xor_sync(0xffffffffu, d1, off);
            d2 += __shfl_xor_sync(0xffffffffu, d2, off);
        }

        float a1 = E.x * d1;
        float a2 = E.y * fmaf(-E.z, d1, d2);

        h0 = fmaf(-a2, Cv.x, fmaf(-a1, A.x, z0 + Bv.x));
        h1 = fmaf(-a2, Cv.y, fmaf(-a1, A.y, z1 + Bv.y));
        h2 = fmaf(-a2, Cv.z, fmaf(-a1, A.z, y2 + Bv.z));
        h3 = fmaf(-a2, Cv.w, fmaf(-a1, A.w, y3 + Bv.w));

        // pack 12 bf16 (hh0,hl0,hh0, hh1,hl1,hh1, hh2,hl2,hh2, hh3,hl3,hh3) -> 3 x STG.64
        __nv_bfloat16 hh0, hl0, hh1, hl1, hh2, hl2, hh3, hl3;
        split_bf16(h0, hh0, hl0); split_bf16(h1, hh1, hl1);
        split_bf16(h2, hh2, hl2); split_bf16(h3, hh3, hl3);
        unsigned w0 = pack2(hh0, hl0);
        unsigned w1 = pack2(hh0, hh1);
        unsigned w2 = pack2(hl1, hh1);
        unsigned w3 = pack2(hh2, hl2);
        unsigned w4 = pack2(hh2, hh3);
        unsigned w5 = pack2(hl3, hh3);
        uint2* op = (uint2*)(o + (size_t)t * K2EXP) + 3 * lane;
        op[0] = make_uint2(w0, w1);
        op[1] = make_uint2(w2, w3);
        op[2] = make_uint2(w4, w5);
    }
}

// ---------------- launch ----------------
extern "C" void kernel_launch(void* const* d_in, const int* in_sizes, int n_in,
                              void* d_out, int out_size)
{
    const float* u      = (const float*)d_in[0];
    const float* W_A    = (const float*)d_in[1];
    const float* b_A    = (const float*)d_in[2];
    const float* W_k    = (const float*)d_in[3];
    const float* b_k    = (const float*)d_in[4];
    const float* W_beta = (const float*)d_in[5];
    const float* b_beta = (const float*)d_in[6];
    const float* B_w    = (const float*)d_in[7];
    const float* B_b    = (const float*)d_in[8];
    const float* C      = (const float*)d_in[9];
    const float* D      = (const float*)d_in[10];
    float* out = (float*)d_out;

    pack_b1<<<(NP * DMODEL + 255) / 256, 256>>>(W_A, W_k, W_beta, B_w);
    pack_b2<<<(DMODEL * 128 + 255) / 256, 256>>>(C);
    conv_u<<<(BT * (DMODEL / 4)) / 256, 256>>>(u);

    // GEMM1: P[16384 x 512] = Uexp[16384 x 3072] * B1^T
    {
        __nv_bfloat16 *dA, *dB; float* dP;
        cudaGetSymbolAddress((void**)&dA, g_Uexp);
        cudaGetSymbolAddress((void**)&dB, g_B1);
        cudaGetSymbolAddress((void**)&dP, g_P);
        mma_gemm<K1EXP, K1EXP, K1EXP><<<dim3(NP / 128, BT / 128), 256>>>(
            dA, dB, dP, NP, nullptr, nullptr);
    }

    derive_kernel<<<BT, 128>>>(b_A, b_k, b_beta, B_b);

    scan_kernel<<<BATCH, 32>>>();

    // GEMM2: out[16384 x 1024] = Hexp[16384 x 384] * B2^T + u * D
    {
        __nv_bfloat16 *dA, *dB;
        cudaGetSymbolAddress((void**)&dA, g_Hexp);
        cudaGetSymbolAddress((void**)&dB, g_B2);
        mma_gemm<K2EXP, K2EXP, K2EXP><<<dim3(DMODEL / 128, BT / 128), 256>>>(
            dA, dB, out, DMODEL, u, D);
    }
}